// round 1
// baseline (speedup 1.0000x reference)
#include <cuda_runtime.h>
#include <cuda_bf16.h>

// Problem constants (match reference)
#define BN       4096
#define L_SB     3968
#define L_M2IN   4800
#define M2TRUNC  3968
#define HALF     40        // WIN//2
#define RAMP_MAX 200
#define N_Q      992       // L_SB / 4 (float4 count per row)

__global__ __launch_bounds__(256) void crossfade_kernel(
    const float* __restrict__ sb,      // (B, L_SB)
    const float* __restrict__ m2,      // (B, L_M2IN)
    const float* __restrict__ latent,  // (B, 10)
    const int*   __restrict__ o_sb,    // (B,)
    const int*   __restrict__ o_m,     // (B,)
    float*       __restrict__ out)     // (B, L_SB)
{
    const int b = blockIdx.y;
    const int q = blockIdx.x * blockDim.x + threadIdx.x;   // float4 index in row
    if (q >= N_Q) return;

    // per-row scalars (broadcast loads, cheap)
    const int ss = max(o_sb[b] - HALF, 0);
    const int ms = max(o_m[b]  - HALF, 0);
    const int until = min(L_SB - ss, M2TRUNC - ms);
    const float l0 = latent[b * 10 + 0];
    const float l1 = latent[b * 10 + 1];
    const float l2 = latent[b * 10 + 2];
    const float vol = l0 * l1 * l2;                  // jnp.prod order
    const int   mp  = (int)floorf((0.002f * sqrtf(vol)) * 16000.0f);
    const bool  active = until > mp;
    const int   ramp   = min(max(until - mp, 0), RAMP_MAX);
    const float denom  = (float)max(ramp - 1, 1);

    const size_t rowo = (size_t)b * L_SB;
    const float4 s4 = reinterpret_cast<const float4*>(sb + rowo)[q];
    const float* __restrict__ m2row = m2 + (size_t)b * L_M2IN;

    float sv[4] = { s4.x, s4.y, s4.z, s4.w };
    float rv[4];

    const int j0 = q * 4;
    #pragma unroll
    for (int u = 0; u < 4; u++) {
        const int j = j0 + u;
        const int t = j - ss;
        const int k = t - mp;
        float o = sv[u];
        if (active && k >= 0 && (k < ramp || t < until)) {
            const int mi = min(max(ms + t, 0), M2TRUNC - 1);
            const float m = __ldg(m2row + mi);
            if (k < ramp) {
                float w = (float)k / denom;
                w = fminf(fmaxf(w, 0.0f), 1.0f);
                o = o * (1.0f - w) + m * w;
            } else {
                o = m;   // tail region: k >= ramp && t < until
            }
        }
        rv[u] = o;
    }

    reinterpret_cast<float4*>(out + rowo)[q] =
        make_float4(rv[0], rv[1], rv[2], rv[3]);
}

// Second output: origins = full(B, HALF). Written as float (flattened-concat
// convention: output dtype float32).
__global__ void origins_kernel(float* __restrict__ out, int n_tail)
{
    const int i = blockIdx.x * blockDim.x + threadIdx.x;
    if (i < n_tail) out[(size_t)BN * L_SB + i] = (float)HALF;
}

extern "C" void kernel_launch(void* const* d_in, const int* in_sizes, int n_in,
                              void* d_out, int out_size)
{
    const float* sb     = (const float*)d_in[0];
    const float* m2     = (const float*)d_in[1];
    const float* latent = (const float*)d_in[2];
    const int*   osb    = (const int*)d_in[3];
    const int*   om     = (const int*)d_in[4];
    float* out = (float*)d_out;

    dim3 block(256);
    dim3 grid((N_Q + 255) / 256, BN);
    crossfade_kernel<<<grid, block>>>(sb, m2, latent, osb, om, out);

    const int n_tail = out_size - BN * L_SB;
    if (n_tail > 0) {
        origins_kernel<<<(n_tail + 255) / 256, 256>>>(out, n_tail);
    }
}

// round 2
// speedup vs baseline: 1.3693x; 1.3693x over previous
#include <cuda_runtime.h>
#include <cuda_bf16.h>

// Problem constants (match reference)
#define BN       4096
#define L_SB     3968
#define L_M2IN   4800
#define M2TRUNC  3968
#define HALF     40        // WIN//2
#define RAMP_MAX 200
#define N_Q      992       // L_SB / 4 (float4 count per row)
#define NT       256       // threads per block

__global__ __launch_bounds__(NT) void crossfade_kernel(
    const float* __restrict__ sb,      // (B, L_SB)
    const float* __restrict__ m2,      // (B, L_M2IN)
    const float* __restrict__ latent,  // (B, 10)
    const int*   __restrict__ o_sb,    // (B,)
    const int*   __restrict__ o_m,     // (B,)
    float*       __restrict__ out,     // (B, L_SB) then (B,) origins
    int n_tail)
{
    const int b   = blockIdx.x;
    const int tid = threadIdx.x;

    // ---- per-row scalars (broadcast loads, computed once per thread) ----
    const int ss = max(o_sb[b] - HALF, 0);
    const int ms = max(o_m[b]  - HALF, 0);
    const int until = min(L_SB - ss, M2TRUNC - ms);
    const float l0 = latent[b * 10 + 0];
    const float l1 = latent[b * 10 + 1];
    const float l2 = latent[b * 10 + 2];
    const float vol = l0 * l1 * l2;                        // jnp.prod order
    const int   mp  = (int)floorf((0.002f * sqrtf(vol)) * 16000.0f);
    const bool  active = until > mp;
    const int   ramp   = min(max(until - mp, 0), RAMP_MAX);
    const float denom  = (float)max(ramp - 1, 1);

    // Region boundaries in output index j:
    //   j <  head_end           : pure sb   (k < 0)        [or everything if !active]
    //   head_end <= j < ramp_end: crossfade ramp
    //   ramp_end <= j < tail_end: pure m2   (k>=ramp, t<until)
    //   j >= tail_end           : pure sb
    const int head_end = ss + mp;
    const int ramp_end = head_end + ramp;
    const int tail_end = ss + until;
    const int d        = ms - ss;    // m_idx = j + d (in-range within tail)

    const size_t rowo = (size_t)b * L_SB;
    const float4* __restrict__ sb4  = reinterpret_cast<const float4*>(sb + rowo);
    float4*       __restrict__ out4 = reinterpret_cast<float4*>(out + rowo);
    const float*  __restrict__ m2row = m2 + (size_t)b * L_M2IN;

    #pragma unroll
    for (int it = 0; it < 4; it++) {
        const int q = tid + it * NT;
        if (q >= N_Q) break;
        const int j0 = q * 4;
        const int j3 = j0 + 3;

        float4 o;
        if (!active || j3 < head_end || j0 >= tail_end) {
            // pure shoebox passthrough — no m2 traffic
            o = sb4[q];
        } else if (j0 >= ramp_end && j3 < tail_end) {
            // pure m2 copy — skip the sb load entirely (saves ~75% of sb reads)
            const int mi = j0 + d;
            o.x = __ldg(m2row + mi + 0);
            o.y = __ldg(m2row + mi + 1);
            o.z = __ldg(m2row + mi + 2);
            o.w = __ldg(m2row + mi + 3);
        } else {
            // boundary group (<=3 per row): full per-element logic
            const float4 s4 = sb4[q];
            float sv[4] = { s4.x, s4.y, s4.z, s4.w };
            float rv[4];
            #pragma unroll
            for (int u = 0; u < 4; u++) {
                const int j = j0 + u;
                const int t = j - ss;
                const int k = t - mp;
                float v = sv[u];
                if (k >= 0 && (k < ramp || t < until)) {
                    const int mi = min(max(ms + t, 0), M2TRUNC - 1);
                    const float m = __ldg(m2row + mi);
                    if (k < ramp) {
                        float w = (float)k / denom;
                        w = fminf(fmaxf(w, 0.0f), 1.0f);
                        v = v * (1.0f - w) + m * w;
                    } else {
                        v = m;
                    }
                }
                rv[u] = v;
            }
            o = make_float4(rv[0], rv[1], rv[2], rv[3]);
        }
        out4[q] = o;
    }

    // Fused second output: origins = full(B, HALF) as float (output dtype f32)
    if (tid == 0 && b < n_tail) {
        out[(size_t)BN * L_SB + b] = (float)HALF;
    }
}

extern "C" void kernel_launch(void* const* d_in, const int* in_sizes, int n_in,
                              void* d_out, int out_size)
{
    const float* sb     = (const float*)d_in[0];
    const float* m2     = (const float*)d_in[1];
    const float* latent = (const float*)d_in[2];
    const int*   osb    = (const int*)d_in[3];
    const int*   om     = (const int*)d_in[4];
    float* out = (float*)d_out;

    const int n_tail = out_size - BN * L_SB;
    crossfade_kernel<<<BN, NT>>>(sb, m2, latent, osb, om, out, n_tail);
}

// round 3
// speedup vs baseline: 1.4601x; 1.0663x over previous
#include <cuda_runtime.h>
#include <cuda_bf16.h>

#define BN       4096
#define L_SB     3968
#define L_M2IN   4800
#define M2TRUNC  3968
#define HALF     40        // WIN//2
#define RAMP_MAX 200
#define N_Q      992       // L_SB / 4
#define NT       256

// Full per-element reference logic for one quad (boundary quads only).
__device__ __forceinline__ float4 quad_full(
    const float4* __restrict__ sb4, const float* __restrict__ m2row,
    int q, int ss, int ms, int mp, int until, int ramp, float denom)
{
    const float4 s4 = __ldcs(&sb4[q]);
    float sv[4] = { s4.x, s4.y, s4.z, s4.w };
    float rv[4];
    const int j0 = q * 4;
    #pragma unroll
    for (int u = 0; u < 4; u++) {
        const int j = j0 + u;
        const int t = j - ss;
        const int k = t - mp;
        float v = sv[u];
        if (k >= 0 && (k < ramp || t < until)) {
            const int mi = min(max(ms + t, 0), M2TRUNC - 1);
            const float m = __ldg(m2row + mi);
            if (k < ramp) {
                float w = (float)k / denom;
                w = fminf(fmaxf(w, 0.0f), 1.0f);
                v = v * (1.0f - w) + m * w;
            } else {
                v = m;
            }
        }
        rv[u] = v;
    }
    return make_float4(rv[0], rv[1], rv[2], rv[3]);
}

__global__ __launch_bounds__(NT) void crossfade_kernel(
    const float* __restrict__ sb,      // (B, L_SB)
    const float* __restrict__ m2,      // (B, L_M2IN)
    const float* __restrict__ latent,  // (B, 10)
    const int*   __restrict__ o_sb,    // (B,)
    const int*   __restrict__ o_m,     // (B,)
    float*       __restrict__ out,     // (B, L_SB) then (B,) origins
    int n_tail)
{
    const int b   = blockIdx.x;
    const int tid = threadIdx.x;

    // ---- per-row scalars ----
    const int ss = max(o_sb[b] - HALF, 0);
    const int ms = max(o_m[b]  - HALF, 0);
    const int until = min(L_SB - ss, M2TRUNC - ms);
    const float vol = latent[b*10+0] * latent[b*10+1] * latent[b*10+2];
    const int   mp  = (int)floorf((0.002f * sqrtf(vol)) * 16000.0f);
    const bool  active = until > mp;
    const int   ramp   = min(max(until - mp, 0), RAMP_MAX);
    const float denom  = (float)max(ramp - 1, 1);

    const int head_end = ss + mp;        // first non-sb output index
    const int ramp_end = head_end + ramp;
    const int tail_end = ss + until;     // first post-m2 sb index
    const int d        = ms - ss;        // m_idx = j + d inside pure-m2 tail

    // Quad-range boundaries (per-row uniform -> zero intra-warp divergence)
    int q_h, q_m0, q_m1, q_t;            // [0,q_h) sb | [q_h,q_m0) mixed |
                                         // [q_m0,q_m1) m2 | [max(q_m1,q_m0),q_t) mixed | [q_t,N_Q) sb
    if (active) {
        q_h  = head_end >> 2;            // j3 < head_end
        q_m0 = (ramp_end + 3) >> 2;      // j0 >= ramp_end
        q_m1 = tail_end >> 2;            // j3 < tail_end
        q_t  = (tail_end + 3) >> 2;      // j0 >= tail_end
        if (q_m1 < q_m0) q_m1 = q_m0;    // degenerate: no pure-m2 quads
    } else {
        q_h = N_Q; q_m0 = N_Q; q_m1 = N_Q; q_t = N_Q;
    }

    const size_t rowo = (size_t)b * L_SB;
    const float4* __restrict__ sb4   = reinterpret_cast<const float4*>(sb + rowo);
    float4*       __restrict__ out4  = reinterpret_cast<float4*>(out + rowo);
    const float*  __restrict__ m2row = m2 + (size_t)b * L_M2IN;
    const float4* __restrict__ m2q   = reinterpret_cast<const float4*>(m2row);

    // 1) pure-sb head
    #pragma unroll 4
    for (int q = tid; q < q_h; q += NT)
        __stcs(&out4[q], __ldcs(&sb4[q]));

    // 2) mixed head+ramp (~50 quads)
    for (int q = q_h + tid; q < q_m0; q += NT)
        __stcs(&out4[q], quad_full(sb4, m2row, q, ss, ms, mp, until, ramp, denom));

    // 3) pure-m2 tail: realigned vector copy. mi0 = 4q + d, dm = alignment phase.
    {
        const int dm   = d & 3;              // non-negative mod 4
        const int qoff = (d - dm) >> 2;      // exact (d - dm divisible by 4)
        switch (dm) {
        case 0:
            #pragma unroll 4
            for (int q = q_m0 + tid; q < q_m1; q += NT)
                __stcs(&out4[q], __ldcs(&m2q[q + qoff]));
            break;
        case 1:
            #pragma unroll 2
            for (int q = q_m0 + tid; q < q_m1; q += NT) {
                const float4 A = __ldcs(&m2q[q + qoff]);
                const float4 Bv = __ldcs(&m2q[q + qoff + 1]);
                __stcs(&out4[q], make_float4(A.y, A.z, A.w, Bv.x));
            }
            break;
        case 2:
            #pragma unroll 2
            for (int q = q_m0 + tid; q < q_m1; q += NT) {
                const float4 A = __ldcs(&m2q[q + qoff]);
                const float4 Bv = __ldcs(&m2q[q + qoff + 1]);
                __stcs(&out4[q], make_float4(A.z, A.w, Bv.x, Bv.y));
            }
            break;
        default:
            #pragma unroll 2
            for (int q = q_m0 + tid; q < q_m1; q += NT) {
                const float4 A = __ldcs(&m2q[q + qoff]);
                const float4 Bv = __ldcs(&m2q[q + qoff + 1]);
                __stcs(&out4[q], make_float4(A.w, Bv.x, Bv.y, Bv.z));
            }
            break;
        }
    }

    // 4) mixed tail boundary (<=1-2 quads)
    for (int q = q_m1 + tid; q < q_t; q += NT)
        __stcs(&out4[q], quad_full(sb4, m2row, q, ss, ms, mp, until, ramp, denom));

    // 5) pure-sb tail
    #pragma unroll 4
    for (int q = q_t + tid; q < N_Q; q += NT)
        __stcs(&out4[q], __ldcs(&sb4[q]));

    // fused second output: origins = full(B, HALF) as f32
    if (tid == 0 && b < n_tail)
        out[(size_t)BN * L_SB + b] = (float)HALF;
}

extern "C" void kernel_launch(void* const* d_in, const int* in_sizes, int n_in,
                              void* d_out, int out_size)
{
    const float* sb     = (const float*)d_in[0];
    const float* m2     = (const float*)d_in[1];
    const float* latent = (const float*)d_in[2];
    const int*   osb    = (const int*)d_in[3];
    const int*   om     = (const int*)d_in[4];
    float* out = (float*)d_out;

    const int n_tail = out_size - BN * L_SB;
    crossfade_kernel<<<BN, NT>>>(sb, m2, latent, osb, om, out, n_tail);
}